// round 10
// baseline (speedup 1.0000x reference)
#include <cuda_runtime.h>

#define NN 100000
#define NE 1600000
#define F  128

// ---- scratch (device globals: no allocation allowed) ----
__device__ float  g_w[NE];            // per-edge raw weight
__device__ float  g_doutw[NN];        // weighted out-degree
__device__ float  g_dinw[NN];         // weighted in-degree
__device__ int    g_cntin[NN];        // unweighted in-degree (int)
__device__ int    g_cntout[NN];       // unweighted out-degree (int)
__device__ int    g_off[NN + 1];      // CSR offsets by dst
__device__ int    g_cursor[NN];       // fill cursors
__device__ float2 g_csr[NE];          // {src (bits), normalized w}
__device__ float  g_normout[NN];      // deg_out^-0.5 (clamped)
__device__ float  g_normin[NN];       // deg_in^-0.5 (clamped)
__device__ float  g_h[(size_t)NN * F];   // GEMM output (both layers)
__device__ float  g_h2[(size_t)NN * F];  // layer-1 activation

// ---------------------------------------------------------------------------
// zero counters
// ---------------------------------------------------------------------------
__global__ void zero_stats_kernel() {
    int i = blockIdx.x * blockDim.x + threadIdx.x;
    if (i < NN) {
        g_doutw[i] = 0.f; g_dinw[i] = 0.f;
        g_cntin[i] = 0; g_cntout[i] = 0; g_cursor[i] = 0;
    }
}

// ---------------------------------------------------------------------------
// edge weight = edge_feats @ W_ef + b; accumulate weighted + unweighted degrees
// ---------------------------------------------------------------------------
__global__ void __launch_bounds__(256) edge_w_kernel(
    const float* __restrict__ edge_feats, const float* __restrict__ W_ef,
    const float* __restrict__ b_ef, const int* __restrict__ src,
    const int* __restrict__ dst)
{
    __shared__ float wef[16];
    __shared__ float bef;
    if (threadIdx.x < 16) wef[threadIdx.x] = W_ef[threadIdx.x];
    if (threadIdx.x == 0) bef = b_ef[0];
    __syncthreads();

    int e = blockIdx.x * blockDim.x + threadIdx.x;
    if (e >= NE) return;

    const float4* ef = (const float4*)(edge_feats + (size_t)e * 16);
    float s = bef;
#pragma unroll
    for (int i = 0; i < 4; i++) {
        float4 a = ef[i];
        s += a.x * wef[4 * i + 0] + a.y * wef[4 * i + 1]
           + a.z * wef[4 * i + 2] + a.w * wef[4 * i + 3];
    }
    g_w[e] = s;
    int si = src[e], di = dst[e];
    atomicAdd(&g_doutw[si], s);
    atomicAdd(&g_dinw[di], s);
    atomicAdd(&g_cntout[si], 1);
    atomicAdd(&g_cntin[di], 1);
}

// ---------------------------------------------------------------------------
// per-node symmetric norms from unweighted degrees (clamped >= 1)
// ---------------------------------------------------------------------------
__global__ void node_norm_kernel() {
    int i = blockIdx.x * blockDim.x + threadIdx.x;
    if (i < NN) {
        g_normout[i] = rsqrtf((float)max(g_cntout[i], 1));
        g_normin[i]  = rsqrtf((float)max(g_cntin[i], 1));
    }
}

// ---------------------------------------------------------------------------
// exclusive scan of g_cntin -> g_off (single block, 1024 threads)
// ---------------------------------------------------------------------------
__global__ void __launch_bounds__(1024) scan_kernel() {
    __shared__ int sh[1024];
    const int CH = (NN + 1023) / 1024;          // 98
    int t = threadIdx.x;
    int lo = t * CH;
    int hi = lo + CH; if (hi > NN) hi = NN;
    int s = 0;
    for (int i = lo; i < hi; i++) s += g_cntin[i];
    sh[t] = s;
    __syncthreads();
    if (t == 0) {
        int run = 0;
        for (int i = 0; i < 1024; i++) { int v = sh[i]; sh[i] = run; run += v; }
        g_off[NN] = run;                        // == NE
    }
    __syncthreads();
    int run = sh[t];
    for (int i = lo; i < hi; i++) { g_off[i] = run; run += g_cntin[i]; }
}

// ---------------------------------------------------------------------------
// counting-sort fill (fused EdgeWeightNorm): slot per edge within its dst
// segment; pack {src, w / sqrt(doutw[src]*dinw[dst])}
// ---------------------------------------------------------------------------
__global__ void __launch_bounds__(256) csr_fill_kernel(
    const int* __restrict__ src, const int* __restrict__ dst)
{
    int e = blockIdx.x * blockDim.x + threadIdx.x;
    if (e >= NE) return;
    int s = src[e], d = dst[e];
    float w = g_w[e] * rsqrtf(g_doutw[s] * g_dinw[d]);
    int pos = g_off[d] + atomicAdd(&g_cursor[d], 1);
    g_csr[pos] = make_float2(__int_as_float(s), w);
}

// ---------------------------------------------------------------------------
// out[n,:] = (A[n,:] * g_normout[n]) @ W     (A: NNx128 row-major, W: 128x128)
// 64-row x 128-col tile per block, 256 threads, 32-wide k chunks.
// Thread (tx, ty) owns rows ty*8..ty*8+7 (consecutive) x cols tx*4..tx*4+3,
// so the inner loop is 3x LDS.128 + 32 FFMA (vs 12 scalar LDS before).
// ---------------------------------------------------------------------------
__global__ void __launch_bounds__(256) gemm_norm_kernel(
    const float* __restrict__ A, const float* __restrict__ W,
    float* __restrict__ out)
{
    __shared__ float As[32][68];    // [k][row]; 68*4=272B ≡ 16B-aligned rows,
                                    // stride ≡ 4 mod 32 banks -> STS.128 fill
                                    // and LDS.128 reads both conflict-free
    __shared__ float Bs[32][132];   // [k][col]; 132 ≡ 0 mod 4 -> aligned

    int tx = threadIdx.x & 31;      // col group: cols tx*4 .. tx*4+3
    int ty = threadIdx.x >> 5;      // row group: rows ty*8 .. ty*8+7
    int rowbase = blockIdx.x * 64;

    float acc[8][4];
#pragma unroll
    for (int i = 0; i < 8; i++)
#pragma unroll
        for (int j = 0; j < 4; j++) acc[i][j] = 0.f;

    for (int kc = 0; kc < 128; kc += 32) {
        // A tile: warp w loads rows w*8..w*8+7 (warp-uniform row, lane = k col)
        {
            int col = threadIdx.x & 31;     // k within chunk
            int r0  = (threadIdx.x >> 5) * 8;
            float vals[8];
#pragma unroll
            for (int p = 0; p < 8; p++) {
                int grow = rowbase + r0 + p;
                vals[p] = (grow < NN)
                        ? A[(size_t)grow * 128 + kc + col] * g_normout[grow]
                        : 0.f;
            }
            *(float4*)&As[col][r0]     = make_float4(vals[0], vals[1], vals[2], vals[3]);
            *(float4*)&As[col][r0 + 4] = make_float4(vals[4], vals[5], vals[6], vals[7]);
        }
        // B tile: 32 k x 128 cols
        {
#pragma unroll
            for (int p = 0; p < 16; p++) {
                int idx = threadIdx.x + p * 256;
                int k = idx >> 7, c = idx & 127;
                Bs[k][c] = W[(size_t)(kc + k) * 128 + c];
            }
        }
        __syncthreads();
#pragma unroll
        for (int k = 0; k < 32; k++) {
            float4 a0 = *(const float4*)&As[k][ty * 8];      // broadcast
            float4 a1 = *(const float4*)&As[k][ty * 8 + 4];  // broadcast
            float4 bv = *(const float4*)&Bs[k][tx * 4];      // lane-consecutive
            float a[8] = {a0.x, a0.y, a0.z, a0.w, a1.x, a1.y, a1.z, a1.w};
            float b[4] = {bv.x, bv.y, bv.z, bv.w};
#pragma unroll
            for (int i = 0; i < 8; i++)
#pragma unroll
                for (int j = 0; j < 4; j++)
                    acc[i][j] = fmaf(a[i], b[j], acc[i][j]);
        }
        __syncthreads();
    }
#pragma unroll
    for (int i = 0; i < 8; i++) {
        int grow = rowbase + ty * 8 + i;
        if (grow < NN) {
            *(float4*)&out[(size_t)grow * 128 + tx * 4] =
                make_float4(acc[i][0], acc[i][1], acc[i][2], acc[i][3]);
        }
    }
}

// ---------------------------------------------------------------------------
// gather-reduce per dst node (warp per node), fused epilogue:
//   out[n] = relu_opt( (sum_e w_e * h[src_e]) * norm_in[n] + bias )
// No atomics. 2 independent accumulator chains (MLP=2 on the gather stream).
// ---------------------------------------------------------------------------
__global__ void __launch_bounds__(256) gather_kernel(
    const float* __restrict__ h, const float* __restrict__ bias,
    float* __restrict__ outp, int relu)
{
    int n = (blockIdx.x * blockDim.x + threadIdx.x) >> 5;
    int lane = threadIdx.x & 31;
    if (n >= NN) return;

    int base = g_off[n];
    int end  = g_off[n + 1];

    float4 acc0 = make_float4(0.f, 0.f, 0.f, 0.f);
    float4 acc1 = make_float4(0.f, 0.f, 0.f, 0.f);

    int e = base;
    for (; e + 1 < end; e += 2) {
        float2 r0 = g_csr[e];
        float2 r1 = g_csr[e + 1];
        int   s0 = __float_as_int(r0.x);
        int   s1 = __float_as_int(r1.x);
        float w0 = r0.y, w1 = r1.y;
        float4 v0 = __ldg(((const float4*)(h + (size_t)s0 * F)) + lane);
        float4 v1 = __ldg(((const float4*)(h + (size_t)s1 * F)) + lane);
        acc0.x = fmaf(v0.x, w0, acc0.x);
        acc0.y = fmaf(v0.y, w0, acc0.y);
        acc0.z = fmaf(v0.z, w0, acc0.z);
        acc0.w = fmaf(v0.w, w0, acc0.w);
        acc1.x = fmaf(v1.x, w1, acc1.x);
        acc1.y = fmaf(v1.y, w1, acc1.y);
        acc1.z = fmaf(v1.z, w1, acc1.z);
        acc1.w = fmaf(v1.w, w1, acc1.w);
    }
    if (e < end) {
        float2 r0 = g_csr[e];
        int   s0 = __float_as_int(r0.x);
        float w0 = r0.y;
        float4 v0 = __ldg(((const float4*)(h + (size_t)s0 * F)) + lane);
        acc0.x = fmaf(v0.x, w0, acc0.x);
        acc0.y = fmaf(v0.y, w0, acc0.y);
        acc0.z = fmaf(v0.z, w0, acc0.z);
        acc0.w = fmaf(v0.w, w0, acc0.w);
    }

    float4 acc;
    acc.x = acc0.x + acc1.x;
    acc.y = acc0.y + acc1.y;
    acc.z = acc0.z + acc1.z;
    acc.w = acc0.w + acc1.w;

    float  ni = g_normin[n];
    float4 bb = ((const float4*)bias)[lane];
    float4 r;
    r.x = fmaf(acc.x, ni, bb.x);
    r.y = fmaf(acc.y, ni, bb.y);
    r.z = fmaf(acc.z, ni, bb.z);
    r.w = fmaf(acc.w, ni, bb.w);
    if (relu) {
        r.x = fmaxf(r.x, 0.f); r.y = fmaxf(r.y, 0.f);
        r.z = fmaxf(r.z, 0.f); r.w = fmaxf(r.w, 0.f);
    }
    ((float4*)outp)[(size_t)n * (F / 4) + lane] = r;
}

// ---------------------------------------------------------------------------
extern "C" void kernel_launch(void* const* d_in, const int* in_sizes, int n_in,
                              void* d_out, int out_size)
{
    const float* node_feats = (const float*)d_in[0];
    const float* edge_feats = (const float*)d_in[1];
    const float* W_ef       = (const float*)d_in[2];
    const float* b_ef       = (const float*)d_in[3];
    const float* W1         = (const float*)d_in[4];
    const float* b1         = (const float*)d_in[5];
    const float* W2         = (const float*)d_in[6];
    const float* b2         = (const float*)d_in[7];
    const int*   src        = (const int*)d_in[8];
    const int*   dst        = (const int*)d_in[9];
    float*       out        = (float*)d_out;

    float *ph = nullptr, *ph2 = nullptr;
    cudaGetSymbolAddress((void**)&ph,  g_h);
    cudaGetSymbolAddress((void**)&ph2, g_h2);

    const int nodeBlocks   = (NN + 255) / 256;
    const int edgeBlocks   = (NE + 255) / 256;
    const int gatherBlocks = (NN * 32 + 255) / 256;   // one warp per node
    const int gemmBlocks   = (NN + 63) / 64;

    // edge weights + norms + CSR build (once, shared by both layers)
    zero_stats_kernel<<<nodeBlocks, 256>>>();
    edge_w_kernel<<<edgeBlocks, 256>>>(edge_feats, W_ef, b_ef, src, dst);
    node_norm_kernel<<<nodeBlocks, 256>>>();
    scan_kernel<<<1, 1024>>>();
    csr_fill_kernel<<<edgeBlocks, 256>>>(src, dst);   // fused edge-weight norm

    // layer 1: h = (x * norm_out) @ W1 ; h2 = relu(gather * norm_in + b1)
    gemm_norm_kernel<<<gemmBlocks, 256>>>(node_feats, W1, ph);
    gather_kernel<<<gatherBlocks, 256>>>(ph, b1, ph2, 1);

    // layer 2: h = (h2 * norm_out) @ W2 ; out = gather * norm_in + b2
    gemm_norm_kernel<<<gemmBlocks, 256>>>(ph2, W2, ph);
    gather_kernel<<<gatherBlocks, 256>>>(ph, b2, out, 0);
}

// round 11
// speedup vs baseline: 1.6795x; 1.6795x over previous
#include <cuda_runtime.h>

#define NN 100000
#define NE 1600000
#define F  128
#define SCAN_T 512
#define SCAN_NB ((NN + SCAN_T - 1) / SCAN_T)   // 196

// ---- scratch (device globals: no allocation allowed) ----
__device__ float  g_w[NE];            // per-edge raw weight
__device__ float  g_doutw[NN];        // weighted out-degree
__device__ float  g_dinw[NN];         // weighted in-degree
__device__ int    g_cntin[NN];        // unweighted in-degree (int)
__device__ int    g_cntout[NN];       // unweighted out-degree (int)
__device__ int    g_off[NN + 1];      // CSR offsets by dst
__device__ int    g_cursor[NN];       // fill cursors
__device__ int    g_bsum[SCAN_NB];    // scan block sums
__device__ float2 g_csr[NE];          // {src (bits), normalized w}
__device__ float  g_normout[NN];      // deg_out^-0.5 (clamped)
__device__ float  g_normin[NN];       // deg_in^-0.5 (clamped)
__device__ float  g_h[(size_t)NN * F];   // GEMM output (both layers)
__device__ float  g_h2[(size_t)NN * F];  // layer-1 activation

// ---------------------------------------------------------------------------
// zero counters
// ---------------------------------------------------------------------------
__global__ void zero_stats_kernel() {
    int i = blockIdx.x * blockDim.x + threadIdx.x;
    if (i < NN) {
        g_doutw[i] = 0.f; g_dinw[i] = 0.f;
        g_cntin[i] = 0; g_cntout[i] = 0; g_cursor[i] = 0;
    }
}

// ---------------------------------------------------------------------------
// edge weight = edge_feats @ W_ef + b; accumulate weighted + unweighted degrees
// ---------------------------------------------------------------------------
__global__ void __launch_bounds__(256) edge_w_kernel(
    const float* __restrict__ edge_feats, const float* __restrict__ W_ef,
    const float* __restrict__ b_ef, const int* __restrict__ src,
    const int* __restrict__ dst)
{
    __shared__ float wef[16];
    __shared__ float bef;
    if (threadIdx.x < 16) wef[threadIdx.x] = W_ef[threadIdx.x];
    if (threadIdx.x == 0) bef = b_ef[0];
    __syncthreads();

    int e = blockIdx.x * blockDim.x + threadIdx.x;
    if (e >= NE) return;

    const float4* ef = (const float4*)(edge_feats + (size_t)e * 16);
    float s = bef;
#pragma unroll
    for (int i = 0; i < 4; i++) {
        float4 a = ef[i];
        s += a.x * wef[4 * i + 0] + a.y * wef[4 * i + 1]
           + a.z * wef[4 * i + 2] + a.w * wef[4 * i + 3];
    }
    g_w[e] = s;
    int si = src[e], di = dst[e];
    atomicAdd(&g_doutw[si], s);
    atomicAdd(&g_dinw[di], s);
    atomicAdd(&g_cntout[si], 1);
    atomicAdd(&g_cntin[di], 1);
}

// ---------------------------------------------------------------------------
// hierarchical scan, level 1: per-block exclusive prefix of cntin -> g_off,
// block totals -> g_bsum. Also computes node norms (fused elementwise pass).
// ---------------------------------------------------------------------------
__global__ void __launch_bounds__(SCAN_T) scan_blocks_kernel() {
    __shared__ int wsum[16];
    int i = blockIdx.x * SCAN_T + threadIdx.x;
    int v = 0;
    if (i < NN) {
        int cin = g_cntin[i];
        v = cin;
        g_normin[i]  = rsqrtf((float)max(cin, 1));
        g_normout[i] = rsqrtf((float)max(g_cntout[i], 1));
    }
    int lane = threadIdx.x & 31, wid = threadIdx.x >> 5;

    // inclusive warp scan
    int x = v;
#pragma unroll
    for (int d = 1; d < 32; d <<= 1) {
        int y = __shfl_up_sync(0xffffffff, x, d);
        if (lane >= d) x += y;
    }
    if (lane == 31) wsum[wid] = x;
    __syncthreads();
    if (wid == 0) {
        int t = (lane < 16) ? wsum[lane] : 0;
#pragma unroll
        for (int d = 1; d < 16; d <<= 1) {
            int y = __shfl_up_sync(0xffffffff, t, d);
            if (lane >= d) t += y;
        }
        if (lane < 16) wsum[lane] = t;
    }
    __syncthreads();
    int woff = (wid > 0) ? wsum[wid - 1] : 0;
    if (i < NN) g_off[i] = woff + x - v;           // exclusive prefix
    if (threadIdx.x == SCAN_T - 1) g_bsum[blockIdx.x] = woff + x;  // block total
}

// ---------------------------------------------------------------------------
// hierarchical scan, level 2: add prefix of block sums; g_off[NN] = NE
// ---------------------------------------------------------------------------
__global__ void __launch_bounds__(SCAN_T) scan_finish_kernel() {
    __shared__ int sb[SCAN_NB];
    for (int t = threadIdx.x; t < SCAN_NB; t += SCAN_T) sb[t] = g_bsum[t];
    __syncthreads();
    int b = blockIdx.x;
    int S = 0;
    for (int j = 0; j < b; j++) S += sb[j];       // smem broadcast, cheap
    int i = b * SCAN_T + threadIdx.x;
    if (i < NN) g_off[i] += S;
    if (i == 0) g_off[NN] = NE;                   // total in-degree == #edges
}

// ---------------------------------------------------------------------------
// counting-sort fill (fused EdgeWeightNorm): slot per edge within its dst
// segment; pack {src, w / sqrt(doutw[src]*dinw[dst])}
// ---------------------------------------------------------------------------
__global__ void __launch_bounds__(256) csr_fill_kernel(
    const int* __restrict__ src, const int* __restrict__ dst)
{
    int e = blockIdx.x * blockDim.x + threadIdx.x;
    if (e >= NE) return;
    int s = src[e], d = dst[e];
    float w = g_w[e] * rsqrtf(g_doutw[s] * g_dinw[d]);
    int pos = g_off[d] + atomicAdd(&g_cursor[d], 1);
    g_csr[pos] = make_float2(__int_as_float(s), w);
}

// ---------------------------------------------------------------------------
// out[n,:] = (A[n,:] * g_normout[n]) @ W     (A: NNx128 row-major, W: 128x128)
// 64-row x 128-col tile per block, 256 threads, 32-wide k chunks
// (R8-measured version: part of the 557.5us passing config)
// ---------------------------------------------------------------------------
__global__ void __launch_bounds__(256) gemm_norm_kernel(
    const float* __restrict__ A, const float* __restrict__ W,
    float* __restrict__ out)
{
    __shared__ float As[32][65];    // [k][row], padded: conflict-free both ways
    __shared__ float Bs[32][132];   // [k][col]

    int tx = threadIdx.x & 31;      // output col group base
    int ty = threadIdx.x >> 5;      // output row group base (0..7)
    int rowbase = blockIdx.x * 64;

    float acc[8][4];
#pragma unroll
    for (int i = 0; i < 8; i++)
#pragma unroll
        for (int j = 0; j < 4; j++) acc[i][j] = 0.f;

    for (int kc = 0; kc < 128; kc += 32) {
        // A tile: 64 rows x 32 k, scaled by norm_out, stored transposed
        {
            int col = threadIdx.x & 31;
            int r0  = threadIdx.x >> 5;
#pragma unroll
            for (int p = 0; p < 8; p++) {
                int r = r0 + p * 8;
                int grow = rowbase + r;
                float v = 0.f;
                if (grow < NN) v = A[(size_t)grow * 128 + kc + col] * g_normout[grow];
                As[col][r] = v;
            }
        }
        // B tile: 32 k x 128 cols
        {
#pragma unroll
            for (int p = 0; p < 16; p++) {
                int idx = threadIdx.x + p * 256;
                int k = idx >> 7, c = idx & 127;
                Bs[k][c] = W[(size_t)(kc + k) * 128 + c];
            }
        }
        __syncthreads();
#pragma unroll
        for (int k = 0; k < 32; k++) {
            float a[8], b[4];
#pragma unroll
            for (int i = 0; i < 8; i++) a[i] = As[k][ty + 8 * i];
#pragma unroll
            for (int j = 0; j < 4; j++) b[j] = Bs[k][tx + 32 * j];
#pragma unroll
            for (int i = 0; i < 8; i++)
#pragma unroll
                for (int j = 0; j < 4; j++)
                    acc[i][j] = fmaf(a[i], b[j], acc[i][j]);
        }
        __syncthreads();
    }
#pragma unroll
    for (int i = 0; i < 8; i++) {
        int grow = rowbase + ty + 8 * i;
        if (grow < NN) {
#pragma unroll
            for (int j = 0; j < 4; j++)
                out[(size_t)grow * 128 + tx + 32 * j] = acc[i][j];
        }
    }
}

// ---------------------------------------------------------------------------
// gather-reduce per dst node (warp per node), fused epilogue:
//   out[n] = relu_opt( (sum_e w_e * h[src_e]) * norm_in[n] + bias )
// No atomics. 2 independent accumulator chains (MLP=2 on the gather stream).
// ---------------------------------------------------------------------------
__global__ void __launch_bounds__(256) gather_kernel(
    const float* __restrict__ h, const float* __restrict__ bias,
    float* __restrict__ outp, int relu)
{
    int n = (blockIdx.x * blockDim.x + threadIdx.x) >> 5;
    int lane = threadIdx.x & 31;
    if (n >= NN) return;

    int base = g_off[n];
    int end  = g_off[n + 1];

    float4 acc0 = make_float4(0.f, 0.f, 0.f, 0.f);
    float4 acc1 = make_float4(0.f, 0.f, 0.f, 0.f);

    int e = base;
    for (; e + 1 < end; e += 2) {
        float2 r0 = g_csr[e];
        float2 r1 = g_csr[e + 1];
        int   s0 = __float_as_int(r0.x);
        int   s1 = __float_as_int(r1.x);
        float w0 = r0.y, w1 = r1.y;
        float4 v0 = __ldg(((const float4*)(h + (size_t)s0 * F)) + lane);
        float4 v1 = __ldg(((const float4*)(h + (size_t)s1 * F)) + lane);
        acc0.x = fmaf(v0.x, w0, acc0.x);
        acc0.y = fmaf(v0.y, w0, acc0.y);
        acc0.z = fmaf(v0.z, w0, acc0.z);
        acc0.w = fmaf(v0.w, w0, acc0.w);
        acc1.x = fmaf(v1.x, w1, acc1.x);
        acc1.y = fmaf(v1.y, w1, acc1.y);
        acc1.z = fmaf(v1.z, w1, acc1.z);
        acc1.w = fmaf(v1.w, w1, acc1.w);
    }
    if (e < end) {
        float2 r0 = g_csr[e];
        int   s0 = __float_as_int(r0.x);
        float w0 = r0.y;
        float4 v0 = __ldg(((const float4*)(h + (size_t)s0 * F)) + lane);
        acc0.x = fmaf(v0.x, w0, acc0.x);
        acc0.y = fmaf(v0.y, w0, acc0.y);
        acc0.z = fmaf(v0.z, w0, acc0.z);
        acc0.w = fmaf(v0.w, w0, acc0.w);
    }

    float4 acc;
    acc.x = acc0.x + acc1.x;
    acc.y = acc0.y + acc1.y;
    acc.z = acc0.z + acc1.z;
    acc.w = acc0.w + acc1.w;

    float  ni = g_normin[n];
    float4 bb = ((const float4*)bias)[lane];
    float4 r;
    r.x = fmaf(acc.x, ni, bb.x);
    r.y = fmaf(acc.y, ni, bb.y);
    r.z = fmaf(acc.z, ni, bb.z);
    r.w = fmaf(acc.w, ni, bb.w);
    if (relu) {
        r.x = fmaxf(r.x, 0.f); r.y = fmaxf(r.y, 0.f);
        r.z = fmaxf(r.z, 0.f); r.w = fmaxf(r.w, 0.f);
    }
    ((float4*)outp)[(size_t)n * (F / 4) + lane] = r;
}

// ---------------------------------------------------------------------------
extern "C" void kernel_launch(void* const* d_in, const int* in_sizes, int n_in,
                              void* d_out, int out_size)
{
    const float* node_feats = (const float*)d_in[0];
    const float* edge_feats = (const float*)d_in[1];
    const float* W_ef       = (const float*)d_in[2];
    const float* b_ef       = (const float*)d_in[3];
    const float* W1         = (const float*)d_in[4];
    const float* b1         = (const float*)d_in[5];
    const float* W2         = (const float*)d_in[6];
    const float* b2         = (const float*)d_in[7];
    const int*   src        = (const int*)d_in[8];
    const int*   dst        = (const int*)d_in[9];
    float*       out        = (float*)d_out;

    float *ph = nullptr, *ph2 = nullptr;
    cudaGetSymbolAddress((void**)&ph,  g_h);
    cudaGetSymbolAddress((void**)&ph2, g_h2);

    const int nodeBlocks   = (NN + 255) / 256;
    const int edgeBlocks   = (NE + 255) / 256;
    const int gatherBlocks = (NN * 32 + 255) / 256;   // one warp per node
    const int gemmBlocks   = (NN + 63) / 64;

    // prologue: 5 launches -> ncu (-s 5) profiles gemm #1 next
    zero_stats_kernel<<<nodeBlocks, 256>>>();                      // 0
    edge_w_kernel<<<edgeBlocks, 256>>>(edge_feats, W_ef, b_ef, src, dst); // 1
    scan_blocks_kernel<<<SCAN_NB, SCAN_T>>>();                     // 2 (+ node norms)
    scan_finish_kernel<<<SCAN_NB, SCAN_T>>>();                     // 3
    csr_fill_kernel<<<edgeBlocks, 256>>>(src, dst);                // 4 (fused edge norm)

    // layer 1: h = (x * norm_out) @ W1 ; h2 = relu(gather * norm_in + b1)
    gemm_norm_kernel<<<gemmBlocks, 256>>>(node_feats, W1, ph);     // 5 <- profiled
    gather_kernel<<<gatherBlocks, 256>>>(ph, b1, ph2, 1);

    // layer 2: h = (h2 * norm_out) @ W2 ; out = gather * norm_in + b2
    gemm_norm_kernel<<<gemmBlocks, 256>>>(ph2, W2, ph);
    gather_kernel<<<gatherBlocks, 256>>>(ph, b2, out, 0);
}